// round 4
// baseline (speedup 1.0000x reference)
#include <cuda_runtime.h>
#include <cstdint>

// Problem constants (fixed by reference setup_inputs)
#define C_CLS 256
#define S_SUP 5
#define Q_QRY 64
#define DIN   1024
#define ZD    128
#define CS    (C_CLS*S_SUP)              // 1280
#define CQ    (C_CLS*Q_QRY)              // 16384
#define M_TOT (CS+CQ)                    // 17664
#define NPAIRS (C_CLS*(Q_QRY*(Q_QRY-1)/2)) // 516096
#define EPSF  1e-8f

typedef unsigned long long u64;

// ---------------- device scratch (no allocations allowed) ----------------
__device__ __align__(16) float g_z[(size_t)M_TOT * ZD];        // ~9 MB
__device__ __align__(16) float g_d2[(size_t)CQ * C_CLS];       // 16 MB
__device__ __align__(16) float g_protoT[ZD * C_CLS];           // [k][c]
__device__ __align__(16) float g_proto2[C_CLS];                // ||proto_c||^2
__device__ __align__(16) float g_row2[M_TOT];                  // ||z_row||^2
__device__ float g_cos_sum;
__device__ float g_acc_cnt;

// ---------------- packed fp32x2 helpers (Blackwell FFMA2) ----------------
__device__ __forceinline__ u64 pack2(float x, float y){
    u64 r; asm("mov.b64 %0, {%1, %2};" : "=l"(r) : "f"(x), "f"(y)); return r;
}
__device__ __forceinline__ void fma2(u64 &d, u64 a, u64 b){
    asm("fma.rn.f32x2 %0, %1, %2, %0;" : "+l"(d) : "l"(a), "l"(b));
}
__device__ __forceinline__ float2 unpack2(u64 v){
    float lo, hi; asm("mov.b64 {%0, %1}, %2;" : "=f"(lo), "=f"(hi) : "l"(v));
    return make_float2(lo, hi);
}

// =====================================================================
// K1: z = [xs; xq] @ W  (M=17664, K=1024, N=128), fp32 FFMA2.
// 512 threads/CTA (16 warps/SM -> 4/SMSP for latency hiding).
// Tile 128x128, BK=16, double-buffered. Thread (tx,ty): rows 4ty..4ty+3,
// cols {4tx..4tx+3} u {64+4tx..4tx+3} (dense, conflict-free LDS.128).
// Epilogue fuses per-row ||z||^2.
// =====================================================================
#define BK 16
__global__ __launch_bounds__(512) void k_gemm(const float* __restrict__ xs,
                                              const float* __restrict__ xq,
                                              const float* __restrict__ W){
    __shared__ __align__(16) u64   As2[2][BK][128];   // A duplicated (a,a): 32 KB
    __shared__ __align__(16) float Bs [2][BK][128];   // 16 KB  (total 48 KB)
    const int tid = threadIdx.x;
    const int tx = tid & 15, ty = tid >> 4;           // ty: 0..31
    const int bm = blockIdx.x;
    const float* X = (bm < 10) ? (xs + (size_t)bm * (128 * DIN))
                               : (xq + (size_t)(bm - 10) * (128 * DIN));
    const int lm = tid >> 2;            // A row (0..127)
    const int lk = (tid & 3) << 2;      // A k quad
    const int bk = tid >> 5;            // B k row (0..15)
    const int bn = (tid & 31) << 2;     // B n chunk

    u64 acc[4][4];
#pragma unroll
    for (int i = 0; i < 4; i++)
#pragma unroll
        for (int j = 0; j < 4; j++) acc[i][j] = 0ull;

    float4 a0, b0;
    a0 = *(const float4*)(X + (size_t)lm * DIN + lk);
    b0 = *(const float4*)(W + (size_t)bk * ZD + bn);
    As2[0][lk + 0][lm] = pack2(a0.x, a0.x);
    As2[0][lk + 1][lm] = pack2(a0.y, a0.y);
    As2[0][lk + 2][lm] = pack2(a0.z, a0.z);
    As2[0][lk + 3][lm] = pack2(a0.w, a0.w);
    *(float4*)&Bs[0][bk][bn] = b0;
    __syncthreads();

    int buf = 0;
    const int nT = DIN / BK;   // 64
    for (int kt = 0; kt < nT; kt++){
        if (kt + 1 < nT){
            const int kb = (kt + 1) * BK;
            a0 = *(const float4*)(X + (size_t)lm * DIN + kb + lk);
            b0 = *(const float4*)(W + (size_t)(kb + bk) * ZD + bn);
        }
#pragma unroll
        for (int k = 0; k < BK; k++){
            const ulonglong2 aP = *(const ulonglong2*)&As2[buf][k][ty * 4 + 0];
            const ulonglong2 aQ = *(const ulonglong2*)&As2[buf][k][ty * 4 + 2];
            const ulonglong2 bL = *(const ulonglong2*)&Bs[buf][k][tx * 4];
            const ulonglong2 bH = *(const ulonglong2*)&Bs[buf][k][64 + tx * 4];
            const u64 av[4] = {aP.x, aP.y, aQ.x, aQ.y};
#pragma unroll
            for (int i = 0; i < 4; i++){
                fma2(acc[i][0], av[i], bL.x);
                fma2(acc[i][1], av[i], bL.y);
                fma2(acc[i][2], av[i], bH.x);
                fma2(acc[i][3], av[i], bH.y);
            }
        }
        if (kt + 1 < nT){
            const int nb = buf ^ 1;
            As2[nb][lk + 0][lm] = pack2(a0.x, a0.x);
            As2[nb][lk + 1][lm] = pack2(a0.y, a0.y);
            As2[nb][lk + 2][lm] = pack2(a0.z, a0.z);
            As2[nb][lk + 3][lm] = pack2(a0.w, a0.w);
            *(float4*)&Bs[nb][bk][bn] = b0;
            __syncthreads();
            buf = nb;
        }
    }

    // epilogue: store z, fuse row norms (16 tx lanes cover the 128 cols)
    const size_t rb = (size_t)bm * 128;
#pragma unroll
    for (int i = 0; i < 4; i++){
        float s = 0.0f;
#pragma unroll
        for (int j = 0; j < 4; j++){
            const float2 f = unpack2(acc[i][j]);
            s = fmaf(f.x, f.x, s);
            s = fmaf(f.y, f.y, s);
        }
#pragma unroll
        for (int off = 1; off <= 8; off <<= 1)
            s += __shfl_xor_sync(0xffffffffu, s, off);
        const size_t row = rb + ty * 4 + i;
        if (tx == 0) g_row2[row] = s;
        float* zr = g_z + row * ZD;
        *(ulonglong2*)(zr + 4 * tx)      = make_ulonglong2(acc[i][0], acc[i][1]);
        *(ulonglong2*)(zr + 64 + 4 * tx) = make_ulonglong2(acc[i][2], acc[i][3]);
    }
}

// ---------------- K2: prototypes (mean over S=5) + ||proto||^2 -----------
// Also zeroes the global accumulators (runs before k_loo in stream order).
__global__ __launch_bounds__(128) void k_proto(){
    const int c = blockIdx.x;
    const int d = threadIdx.x;  // 0..127
    if (c == 0 && d == 0){ g_cos_sum = 0.0f; g_acc_cnt = 0.0f; }
    const float* z = g_z + (size_t)c * S_SUP * ZD + d;
    float p = 0.0f;
#pragma unroll
    for (int s = 0; s < S_SUP; s++) p += z[s * ZD];
    p *= (1.0f / S_SUP);
    g_protoT[d * C_CLS + c] = p;
    float sq = p * p;
#pragma unroll
    for (int off = 16; off; off >>= 1) sq += __shfl_xor_sync(0xffffffffu, sq, off);
    __shared__ float w[4];
    if ((d & 31) == 0) w[d >> 5] = sq;
    __syncthreads();
    if (d == 0) g_proto2[c] = w[0] + w[1] + w[2] + w[3];
}

// =====================================================================
// K3: d2 = ||zq||^2 + ||proto||^2 - 2 zq@protoT  (16384 x 256 x 128).
// 512 threads, grid 128 (one CTA per 128-query tile), full N=256 per CTA.
// protoT (128KB) fully resident in SMEM; A streamed in BK=16 double-buffered
// chunks. Thread (tx,ty): rows 4ty..+3, cols {4tx,64+4tx,128+4tx,192+4tx}+0..3.
// =====================================================================
__global__ __launch_bounds__(512) void k_d2(){
    extern __shared__ float sm[];
    float* Bsf = sm;                          // [128][256] floats = 128 KB
    u64*   A站 = (u64*)(sm + 32768);          // [2][16][128] u64 = 32 KB
    u64*   As2 = A站;
    const int tid = threadIdx.x;
    const int tx = tid & 15, ty = tid >> 4;   // ty 0..31
    const int qb = blockIdx.x;                // 0..127
    const float* A = g_z + (size_t)(CS + qb * 128) * ZD;
    const int lm = tid >> 2, lk = (tid & 3) << 2;

    // stage full protoT (layout-identical copy, coalesced)
    const float4* src = (const float4*)g_protoT;
    float4* dst = (float4*)Bsf;
    for (int e = tid; e < 8192; e += 512) dst[e] = src[e];

    // stage A chunk 0 (duplicated pairs)
    float4 a0 = *(const float4*)(A + (size_t)lm * ZD + lk);
    As2[(0 * BK + lk + 0) * 128 + lm] = pack2(a0.x, a0.x);
    As2[(0 * BK + lk + 1) * 128 + lm] = pack2(a0.y, a0.y);
    As2[(0 * BK + lk + 2) * 128 + lm] = pack2(a0.z, a0.z);
    As2[(0 * BK + lk + 3) * 128 + lm] = pack2(a0.w, a0.w);
    __syncthreads();

    u64 acc[4][8];
#pragma unroll
    for (int i = 0; i < 4; i++)
#pragma unroll
        for (int j = 0; j < 8; j++) acc[i][j] = 0ull;

    int buf = 0;
    const int nT = ZD / BK;   // 8
    for (int kt = 0; kt < nT; kt++){
        if (kt + 1 < nT)
            a0 = *(const float4*)(A + (size_t)lm * ZD + (kt + 1) * BK + lk);
#pragma unroll
        for (int k = 0; k < BK; k++){
            const float* brow = Bsf + (kt * BK + k) * 256;
            const ulonglong2 aP = *(const ulonglong2*)&As2[(buf * BK + k) * 128 + ty * 4 + 0];
            const ulonglong2 aQ = *(const ulonglong2*)&As2[(buf * BK + k) * 128 + ty * 4 + 2];
            const ulonglong2 b0 = *(const ulonglong2*)&brow[tx * 4];
            const ulonglong2 b1 = *(const ulonglong2*)&brow[64 + tx * 4];
            const ulonglong2 b2 = *(const ulonglong2*)&brow[128 + tx * 4];
            const ulonglong2 b3 = *(const ulonglong2*)&brow[192 + tx * 4];
            const u64 av[4] = {aP.x, aP.y, aQ.x, aQ.y};
#pragma unroll
            for (int i = 0; i < 4; i++){
                fma2(acc[i][0], av[i], b0.x);
                fma2(acc[i][1], av[i], b0.y);
                fma2(acc[i][2], av[i], b1.x);
                fma2(acc[i][3], av[i], b1.y);
                fma2(acc[i][4], av[i], b2.x);
                fma2(acc[i][5], av[i], b2.y);
                fma2(acc[i][6], av[i], b3.x);
                fma2(acc[i][7], av[i], b3.y);
            }
        }
        if (kt + 1 < nT){
            const int nb = buf ^ 1;
            As2[(nb * BK + lk + 0) * 128 + lm] = pack2(a0.x, a0.x);
            As2[(nb * BK + lk + 1) * 128 + lm] = pack2(a0.y, a0.y);
            As2[(nb * BK + lk + 2) * 128 + lm] = pack2(a0.z, a0.z);
            As2[(nb * BK + lk + 3) * 128 + lm] = pack2(a0.w, a0.w);
            __syncthreads();
            buf = nb;
        }
    }

    // epilogue: d2 = qn + pn - 2*dot
    float4 pn[4];
#pragma unroll
    for (int j = 0; j < 4; j++)
        pn[j] = *(const float4*)&g_proto2[j * 64 + 4 * tx];
#pragma unroll
    for (int i = 0; i < 4; i++){
        const int row = qb * 128 + ty * 4 + i;
        const float qn = g_row2[CS + row];
        float* dr = g_d2 + (size_t)row * C_CLS;
#pragma unroll
        for (int j = 0; j < 4; j++){
            const float2 f0 = unpack2(acc[i][2 * j]);
            const float2 f1 = unpack2(acc[i][2 * j + 1]);
            const float* pj = (const float*)&pn[j];
            float4 dv = make_float4(qn + pj[0] - 2.0f * f0.x,
                                    qn + pj[1] - 2.0f * f0.y,
                                    qn + pj[2] - 2.0f * f1.x,
                                    qn + pj[3] - 2.0f * f1.y);
            *(float4*)(dr + j * 64 + 4 * tx) = dv;
        }
    }
}

// =====================================================================
// K4: per-class loo-norm + cos identity + argmin (register-resident).
// cos: sum_{q<k} a_q.a_k = ( ||sum_q a_q||^2 - sum_q ||a_q||^2 ) / 2
// =====================================================================
__global__ __launch_bounds__(256) void k_loo(){
    __shared__ float s_part[8][256];
    __shared__ float s_red[8];
    __shared__ float s_scal[2];

    const int tid  = threadIdx.x;
    const int c    = blockIdx.x;
    const int w    = tid >> 5;
    const int lane = tid & 31;
    if (tid < 2) s_scal[tid] = 0.0f;
    __syncthreads();

    const float* D = g_d2 + ((size_t)c * Q_QRY + w * 8) * C_CLS + lane * 8;
    float d2v[8][8];
#pragma unroll
    for (int r = 0; r < 8; r++){
        const float4 v0 = *(const float4*)(D + (size_t)r * C_CLS);
        const float4 v1 = *(const float4*)(D + (size_t)r * C_CLS + 4);
        d2v[r][0] = v0.x; d2v[r][1] = v0.y; d2v[r][2] = v0.z; d2v[r][3] = v0.w;
        d2v[r][4] = v1.x; d2v[r][5] = v1.y; d2v[r][6] = v1.z; d2v[r][7] = v1.w;
    }

    float sacc[8];
#pragma unroll
    for (int j = 0; j < 8; j++) sacc[j] = 0.0f;
    float sumA2 = 0.0f;
    float cnt   = 0.0f;

#pragma unroll
    for (int r = 0; r < 8; r++){
        float ss = 0.0f;
        float mv = 3.4e38f;
        int   mi = 1 << 30;
#pragma unroll
        for (int j = 0; j < 8; j++){
            const int   p = lane * 8 + j;
            const float v = d2v[r][j];
            if (v < mv){ mv = v; mi = p; }
            if (p != c) ss = fmaf(v, v, ss);
        }
#pragma unroll
        for (int off = 16; off; off >>= 1){
            ss += __shfl_xor_sync(0xffffffffu, ss, off);
            const float ov = __shfl_xor_sync(0xffffffffu, mv, off);
            const int   oi = __shfl_xor_sync(0xffffffffu, mi, off);
            if (ov < mv || (ov == mv && oi < mi)){ mv = ov; mi = oi; }
        }
        const float inv = 1.0f / fmaxf(sqrtf(ss), EPSF);
#pragma unroll
        for (int j = 0; j < 8; j++){
            const int p = lane * 8 + j;
            if (p != c) sacc[j] = fmaf(d2v[r][j], inv, sacc[j]);
        }
        if (lane == 0){
            sumA2 += ss * inv * inv;
            if (mi == c) cnt += 1.0f;
        }
    }

#pragma unroll
    for (int j = 0; j < 8; j++) s_part[w][lane * 8 + j] = sacc[j];
    if (lane == 0){
        atomicAdd(&s_scal[0], sumA2);
        atomicAdd(&s_scal[1], cnt);
    }
    __syncthreads();

    float col = 0.0f;
#pragma unroll
    for (int w2 = 0; w2 < 8; w2++) col += s_part[w2][tid];
    float sq = col * col;
#pragma unroll
    for (int off = 16; off; off >>= 1) sq += __shfl_xor_sync(0xffffffffu, sq, off);
    if (lane == 0) s_red[w] = sq;
    __syncthreads();
    if (tid == 0){
        float S2 = 0.0f;
#pragma unroll
        for (int i = 0; i < 8; i++) S2 += s_red[i];
        atomicAdd(&g_cos_sum, 0.5f * (S2 - s_scal[0]));
        atomicAdd(&g_acc_cnt, s_scal[1]);
    }
}

// ---------------- K5: finalize -------------------------------------------
__global__ void k_final(float* __restrict__ out){
    if (threadIdx.x == 0){
        out[0] = g_cos_sum / (float)NPAIRS;
        out[1] = g_acc_cnt / (float)CQ;
    }
}

// ---------------- launch ---------------------------------------------------
extern "C" void kernel_launch(void* const* d_in, const int* in_sizes, int n_in,
                              void* d_out, int out_size){
    const float* xs = (const float*)d_in[0];
    const float* xq = (const float*)d_in[1];
    const float* W  = (const float*)d_in[2];
    float* out = (float*)d_out;
    (void)in_sizes; (void)n_in; (void)out_size;

    const int smem_d2 = 32768 * 4 + 2 * BK * 128 * 8;   // 128KB protoT + 32KB A = 160KB
    cudaFuncSetAttribute(k_d2, cudaFuncAttributeMaxDynamicSharedMemorySize, smem_d2);

    k_gemm<<<M_TOT / 128, 512>>>(xs, xq, W);
    k_proto<<<C_CLS, 128>>>();
    k_d2<<<128, 512, smem_d2>>>();
    k_loo<<<C_CLS, 256>>>();
    k_final<<<1, 1>>>(out);
}

// round 5
// speedup vs baseline: 1.1181x; 1.1181x over previous
#include <cuda_runtime.h>
#include <cstdint>

// Problem constants (fixed by reference setup_inputs)
#define C_CLS 256
#define S_SUP 5
#define Q_QRY 64
#define DIN   1024
#define ZD    128
#define CS    (C_CLS*S_SUP)              // 1280
#define CQ    (C_CLS*Q_QRY)              // 16384
#define M_TOT (CS+CQ)                    // 17664
#define NPAIRS (C_CLS*(Q_QRY*(Q_QRY-1)/2)) // 516096
#define EPSF  1e-8f
#define NSTG  32                          // K stages of 32

typedef unsigned long long u64;

// ---------------- device scratch (no allocations allowed) ----------------
__device__ __align__(16) float g_z[(size_t)M_TOT * ZD];        // ~9 MB
__device__ __align__(16) float g_d2[(size_t)CQ * C_CLS];       // 16 MB
__device__ __align__(16) float g_protoT[ZD * C_CLS];           // [k][c]
__device__ __align__(16) float g_proto2[C_CLS];                // ||proto_c||^2
__device__ __align__(16) float g_row2[M_TOT];                  // ||z_row||^2
// W tf32 hi/lo, pre-laid-out as the exact SMEM B images:
// [stage][kc(4)][n(128)][8 k-permuted floats]
__device__ __align__(16) float g_Wh[NSTG * 4096];              // 512 KB
__device__ __align__(16) float g_Wl[NSTG * 4096];              // 512 KB
__device__ float g_cos_sum;
__device__ float g_acc_cnt;

// ---------------- packed fp32x2 helpers (FFMA2, for k_d2) ----------------
__device__ __forceinline__ u64 pack2(float x, float y){
    u64 r; asm("mov.b64 %0, {%1, %2};" : "=l"(r) : "f"(x), "f"(y)); return r;
}
__device__ __forceinline__ void fma2(u64 &d, u64 a, u64 b){
    asm("fma.rn.f32x2 %0, %1, %2, %0;" : "+l"(d) : "l"(a), "l"(b));
}
__device__ __forceinline__ float2 unpack2(u64 v){
    float lo, hi; asm("mov.b64 {%0, %1}, %2;" : "=f"(lo), "=f"(hi) : "l"(v));
    return make_float2(lo, hi);
}

// ---------------- tf32 helpers (baseline PTX, sm_80+) --------------------
__device__ __forceinline__ float tf32_rna(float a){
    uint32_t r; asm("cvt.rna.tf32.f32 %0, %1;" : "=r"(r) : "f"(a));
    return __uint_as_float(r);
}
// D += A(16x8,row) * B(8x8,col)   tf32 inputs, fp32 accum
__device__ __forceinline__ void mma8(float4 &d, float2 a01, float2 a23, float2 b){
    asm volatile("mma.sync.aligned.m16n8k8.row.col.f32.tf32.tf32.f32 "
        "{%0,%1,%2,%3}, {%4,%5,%6,%7}, {%8,%9}, {%0,%1,%2,%3};"
        : "+f"(d.x), "+f"(d.y), "+f"(d.z), "+f"(d.w)
        : "r"(__float_as_uint(a01.x)), "r"(__float_as_uint(a23.x)),
          "r"(__float_as_uint(a01.y)), "r"(__float_as_uint(a23.y)),
          "r"(__float_as_uint(b.x)),   "r"(__float_as_uint(b.y)));
}

// =====================================================================
// KW: split W[k=1024][n=128] into tf32 hi/lo in the B smem-image layout:
// g_W*[s*4096 + kc*1024 + n*8 + pos], row pos-order [k0,k4,k1,k5,k2,k6,k3,k7].
// Thread t: n = t>>1, h = t&1 writes positions 4h..4h+3 (values [q,q+4,q+1,q+5]
// with q = 2h).
// =====================================================================
__global__ __launch_bounds__(256) void k_wsplit(const float* __restrict__ W){
    const int s   = blockIdx.x;          // stage 0..31
    const int t   = threadIdx.x;
    const int n   = t >> 1;
    const int h   = t & 1;
#pragma unroll
    for (int kc = 0; kc < 4; kc++){
        const int kb = s * 32 + kc * 8 + 2 * h;
        const float v0 = W[(size_t)(kb + 0) * ZD + n];
        const float v1 = W[(size_t)(kb + 1) * ZD + n];
        const float v4 = W[(size_t)(kb + 4) * ZD + n];
        const float v5 = W[(size_t)(kb + 5) * ZD + n];
        const float h0 = tf32_rna(v0), h1 = tf32_rna(v1);
        const float h4 = tf32_rna(v4), h5 = tf32_rna(v5);
        const int off = s * 4096 + kc * 1024 + n * 8 + h * 4;
        *(float4*)&g_Wh[off] = make_float4(h0, h4, h1, h5);
        *(float4*)&g_Wl[off] = make_float4(v0 - h0, v4 - h4, v1 - h1, v5 - h5);
    }
}

// =====================================================================
// K1: z = [xs; xq] @ W via mma.sync tf32 4-pass split (fp32-quality).
// CTA 128x128, 256 threads = 8 warps (warp_m=wid&3 -> 32 rows,
// warp_n=wid>>2 -> 64 cols). BK=32 (4 k8 chunks), double-buffered smem:
// per buf: Ah[4][128][8] | Al | Bh | Bl  (16384 floats = 64KB), 2 bufs.
// Fragment loads are dense conflict-free LDS.64 via the k-permuted rows.
// Epilogue: z + fused ||row||^2.
// =====================================================================
__global__ __launch_bounds__(256) void k_gemm(const float* __restrict__ xs,
                                              const float* __restrict__ xq){
    extern __shared__ float sb[];        // 32768 floats = 128 KB
    __shared__ float s_r2[128];

    const int tid  = threadIdx.x;
    const int lane = tid & 31;
    const int wid  = tid >> 5;
    const int g    = lane >> 2;          // 0..7
    const int tg   = lane & 3;           // 0..3
    const int wm   = wid & 3;            // warp row group
    const int wn   = wid >> 2;           // warp col group
    const int m0   = wm * 32;
    const int n0   = wn * 64;
    const int bm   = blockIdx.x;
    const float* X = (bm < 10) ? (xs + (size_t)bm * (128 * DIN))
                               : (xq + (size_t)(bm - 10) * (128 * DIN));
    const int sm_m = tid >> 1;           // staging row 0..127
    const int sh   = tid & 1;            // staging half

    float4 acc[2][8];
#pragma unroll
    for (int i = 0; i < 2; i++)
#pragma unroll
        for (int j = 0; j < 8; j++) acc[i][j] = make_float4(0.f, 0.f, 0.f, 0.f);

    float4 rA[4];          // raw A values (pos order) per kc
    float4 rBh[4], rBl[4]; // B copy slots

    // ---- LDG stage s into regs ----
    auto ldg_stage = [&](int s){
#pragma unroll
        for (int kc = 0; kc < 4; kc++){
            const float* xp = X + (size_t)sm_m * DIN + s * 32 + kc * 8 + sh * 2;
            const float2 fa = *(const float2*)(xp);       // k: q, q+1
            const float2 fb = *(const float2*)(xp + 4);   // k: q+4, q+5
            rA[kc] = make_float4(fa.x, fb.x, fa.y, fb.y); // pos order
        }
        const float4* wh = (const float4*)(g_Wh + s * 4096);
        const float4* wl = (const float4*)(g_Wl + s * 4096);
#pragma unroll
        for (int i = 0; i < 4; i++){
            rBh[i] = wh[i * 256 + tid];
            rBl[i] = wl[i * 256 + tid];
        }
    };
    // ---- STS regs into buffer b ----
    auto sts_stage = [&](int b){
        float* buf = sb + b * 16384;
#pragma unroll
        for (int kc = 0; kc < 4; kc++){
            const float4 v = rA[kc];
            const float4 hi = make_float4(tf32_rna(v.x), tf32_rna(v.y),
                                          tf32_rna(v.z), tf32_rna(v.w));
            const int off = kc * 1024 + sm_m * 8 + sh * 4;
            *(float4*)&buf[off]        = hi;                              // Ah
            *(float4*)&buf[4096 + off] = make_float4(v.x - hi.x, v.y - hi.y,
                                                     v.z - hi.z, v.w - hi.w); // Al
        }
#pragma unroll
        for (int i = 0; i < 4; i++){
            *(float4*)&buf[ 8192 + (i * 256 + tid) * 4] = rBh[i];
            *(float4*)&buf[12288 + (i * 256 + tid) * 4] = rBl[i];
        }
    };

    ldg_stage(0);
    sts_stage(0);
    __syncthreads();

    for (int s = 0; s < NSTG; s++){
        const int b = s & 1;
        const float* buf = sb + b * 16384;
        if (s + 1 < NSTG) ldg_stage(s + 1);

#pragma unroll
        for (int kc = 0; kc < 4; kc++){
            const float* Ah = buf + kc * 1024;
            const float* Al = Ah + 4096;
            const float* Bh = Ah + 8192;
            const float* Bl = Ah + 12288;
            // B fragments (8 n-tiles x hi/lo)
            float2 bh[8], bl[8];
#pragma unroll
            for (int j = 0; j < 8; j++){
                const int nr = (n0 + j * 8 + g) * 8 + 2 * tg;
                bh[j] = *(const float2*)&Bh[nr];
                bl[j] = *(const float2*)&Bl[nr];
            }
#pragma unroll
            for (int mt = 0; mt < 2; mt++){
                const int r0 = (m0 + mt * 16 + g) * 8 + 2 * tg;
                const int r8 = r0 + 64;                     // +8 rows
                const float2 ah01 = *(const float2*)&Ah[r0];
                const float2 ah23 = *(const float2*)&Ah[r8];
                const float2 al01 = *(const float2*)&Al[r0];
                const float2 al23 = *(const float2*)&Al[r8];
#pragma unroll
                for (int j = 0; j < 8; j++){
                    mma8(acc[mt][j], ah01, ah23, bh[j]);
                    mma8(acc[mt][j], ah01, ah23, bl[j]);
                    mma8(acc[mt][j], al01, al23, bh[j]);
                    mma8(acc[mt][j], al01, al23, bl[j]);
                }
            }
        }
        __syncthreads();
        if (s + 1 < NSTG){
            sts_stage((s + 1) & 1);
            __syncthreads();
        }
    }

    // ---- epilogue: z store + fused row norms ----
    if (tid < 128) s_r2[tid] = 0.0f;
    __syncthreads();

    const size_t rb = (size_t)bm * 128;
#pragma unroll
    for (int mt = 0; mt < 2; mt++){
        const int r0 = m0 + mt * 16 + g;
        float s0 = 0.0f, s1 = 0.0f;
#pragma unroll
        for (int j = 0; j < 8; j++){
            const float4 a = acc[mt][j];
            const int col = n0 + j * 8 + 2 * tg;
            *(float2*)(g_z + (rb + r0) * ZD + col)     = make_float2(a.x, a.y);
            *(float2*)(g_z + (rb + r0 + 8) * ZD + col) = make_float2(a.z, a.w);
            s0 = fmaf(a.x, a.x, s0); s0 = fmaf(a.y, a.y, s0);
            s1 = fmaf(a.z, a.z, s1); s1 = fmaf(a.w, a.w, s1);
        }
        s0 += __shfl_xor_sync(0xffffffffu, s0, 1);
        s0 += __shfl_xor_sync(0xffffffffu, s0, 2);
        s1 += __shfl_xor_sync(0xffffffffu, s1, 1);
        s1 += __shfl_xor_sync(0xffffffffu, s1, 2);
        if (tg == 0){
            atomicAdd(&s_r2[r0],     s0);
            atomicAdd(&s_r2[r0 + 8], s1);
        }
    }
    __syncthreads();
    if (tid < 128) g_row2[rb + tid] = s_r2[tid];
}

// ---------------- K2: prototypes (mean over S=5) + ||proto||^2 -----------
// Also zeroes the global accumulators (stream-ordered before k_loo).
__global__ __launch_bounds__(128) void k_proto(){
    const int c = blockIdx.x;
    const int d = threadIdx.x;  // 0..127
    if (c == 0 && d == 0){ g_cos_sum = 0.0f; g_acc_cnt = 0.0f; }
    const float* z = g_z + (size_t)c * S_SUP * ZD + d;
    float p = 0.0f;
#pragma unroll
    for (int s = 0; s < S_SUP; s++) p += z[s * ZD];
    p *= (1.0f / S_SUP);
    g_protoT[d * C_CLS + c] = p;
    float sq = p * p;
#pragma unroll
    for (int off = 16; off; off >>= 1) sq += __shfl_xor_sync(0xffffffffu, sq, off);
    __shared__ float w[4];
    if ((d & 31) == 0) w[d >> 5] = sq;
    __syncthreads();
    if (d == 0) g_proto2[c] = w[0] + w[1] + w[2] + w[3];
}

// =====================================================================
// K3: d2 = ||zq||^2 + ||proto||^2 - 2 zq@protoT (16384x256x128), FFMA2.
// (R2-measured version: 32.8us.)
// =====================================================================
#define BK 16
__global__ __launch_bounds__(256) void k_d2(){
    __shared__ __align__(16) u64   As2[2][BK][128];
    __shared__ __align__(16) float Bs [2][BK][128];
    const int tid = threadIdx.x;
    const int tx = tid & 15, ty = tid >> 4;
    const int qb = blockIdx.x;          // 0..127 (query tiles)
    const int cb = blockIdx.y;          // 0..1   (proto tiles)
    const float* A  = g_z + (size_t)(CS + qb * 128) * ZD;
    const float* Bp = g_protoT + cb * 128;
    const int lm = tid >> 2, lk = (tid & 3) << 2;
    const int bk = tid >> 5, bn = (tid & 31) << 2;

    u64 acc[8][4];
#pragma unroll
    for (int i = 0; i < 8; i++)
#pragma unroll
        for (int j = 0; j < 4; j++) acc[i][j] = 0ull;

    float4 a0, a1, b0, b1;
    a0 = *(const float4*)(A + (size_t)lm * ZD + lk);
    a1 = *(const float4*)(A + (size_t)(lm + 64) * ZD + lk);
    b0 = *(const float4*)(Bp + (size_t)bk * C_CLS + bn);
    b1 = *(const float4*)(Bp + (size_t)(bk + 8) * C_CLS + bn);
    As2[0][lk + 0][lm]      = pack2(a0.x, a0.x);
    As2[0][lk + 1][lm]      = pack2(a0.y, a0.y);
    As2[0][lk + 2][lm]      = pack2(a0.z, a0.z);
    As2[0][lk + 3][lm]      = pack2(a0.w, a0.w);
    As2[0][lk + 0][lm + 64] = pack2(a1.x, a1.x);
    As2[0][lk + 1][lm + 64] = pack2(a1.y, a1.y);
    As2[0][lk + 2][lm + 64] = pack2(a1.z, a1.z);
    As2[0][lk + 3][lm + 64] = pack2(a1.w, a1.w);
    *(float4*)&Bs[0][bk][bn]     = b0;
    *(float4*)&Bs[0][bk + 8][bn] = b1;
    __syncthreads();

    int buf = 0;
    const int nT = ZD / BK;   // 8
    for (int kt = 0; kt < nT; kt++){
        if (kt + 1 < nT){
            const int kb = (kt + 1) * BK;
            a0 = *(const float4*)(A + (size_t)lm * ZD + kb + lk);
            a1 = *(const float4*)(A + (size_t)(lm + 64) * ZD + kb + lk);
            b0 = *(const float4*)(Bp + (size_t)(kb + bk) * C_CLS + bn);
            b1 = *(const float4*)(Bp + (size_t)(kb + bk + 8) * C_CLS + bn);
        }
#pragma unroll
        for (int k = 0; k < BK; k++){
            const ulonglong2 aA = *(const ulonglong2*)&As2[buf][k][ty * 8 + 0];
            const ulonglong2 aB = *(const ulonglong2*)&As2[buf][k][ty * 8 + 2];
            const ulonglong2 aC = *(const ulonglong2*)&As2[buf][k][ty * 8 + 4];
            const ulonglong2 aD = *(const ulonglong2*)&As2[buf][k][ty * 8 + 6];
            const ulonglong2 bL = *(const ulonglong2*)&Bs[buf][k][tx * 4];
            const ulonglong2 bH = *(const ulonglong2*)&Bs[buf][k][64 + tx * 4];
            const u64 av[8] = {aA.x, aA.y, aB.x, aB.y, aC.x, aC.y, aD.x, aD.y};
#pragma unroll
            for (int i = 0; i < 8; i++){
                fma2(acc[i][0], av[i], bL.x);
                fma2(acc[i][1], av[i], bL.y);
                fma2(acc[i][2], av[i], bH.x);
                fma2(acc[i][3], av[i], bH.y);
            }
        }
        if (kt + 1 < nT){
            const int nb = buf ^ 1;
            As2[nb][lk + 0][lm]      = pack2(a0.x, a0.x);
            As2[nb][lk + 1][lm]      = pack2(a0.y, a0.y);
            As2[nb][lk + 2][lm]      = pack2(a0.z, a0.z);
            As2[nb][lk + 3][lm]      = pack2(a0.w, a0.w);
            As2[nb][lk + 0][lm + 64] = pack2(a1.x, a1.x);
            As2[nb][lk + 1][lm + 64] = pack2(a1.y, a1.y);
            As2[nb][lk + 2][lm + 64] = pack2(a1.z, a1.z);
            As2[nb][lk + 3][lm + 64] = pack2(a1.w, a1.w);
            *(float4*)&Bs[nb][bk][bn]     = b0;
            *(float4*)&Bs[nb][bk + 8][bn] = b1;
            __syncthreads();
            buf = nb;
        }
    }

    const float4 pL = *(const float4*)&g_proto2[cb * 128 + 4 * tx];
    const float4 pH = *(const float4*)&g_proto2[cb * 128 + 64 + 4 * tx];
#pragma unroll
    for (int i = 0; i < 8; i++){
        const int row = qb * 128 + ty * 8 + i;
        const float qn = g_row2[CS + row];
        float2 f0 = unpack2(acc[i][0]);
        float2 f1 = unpack2(acc[i][1]);
        float2 f2 = unpack2(acc[i][2]);
        float2 f3 = unpack2(acc[i][3]);
        float4 dL = make_float4(qn + pL.x - 2.0f * f0.x, qn + pL.y - 2.0f * f0.y,
                                qn + pL.z - 2.0f * f1.x, qn + pL.w - 2.0f * f1.y);
        float4 dH = make_float4(qn + pH.x - 2.0f * f2.x, qn + pH.y - 2.0f * f2.y,
                                qn + pH.z - 2.0f * f3.x, qn + pH.w - 2.0f * f3.y);
        float* dr = g_d2 + (size_t)row * C_CLS + cb * 128;
        *(float4*)(dr + 4 * tx)      = dL;
        *(float4*)(dr + 64 + 4 * tx) = dH;
    }
}

// =====================================================================
// K4: per-class loo-norm + cos identity + argmin (register-resident).
// cos: sum_{q<k} a_q.a_k = ( ||sum_q a_q||^2 - sum_q ||a_q||^2 ) / 2
// =====================================================================
__global__ __launch_bounds__(256) void k_loo(){
    __shared__ float s_part[8][256];
    __shared__ float s_red[8];
    __shared__ float s_scal[2];

    const int tid  = threadIdx.x;
    const int c    = blockIdx.x;
    const int w    = tid >> 5;
    const int lane = tid & 31;
    if (tid < 2) s_scal[tid] = 0.0f;
    __syncthreads();

    const float* D = g_d2 + ((size_t)c * Q_QRY + w * 8) * C_CLS + lane * 8;
    float d2v[8][8];
#pragma unroll
    for (int r = 0; r < 8; r++){
        const float4 v0 = *(const float4*)(D + (size_t)r * C_CLS);
        const float4 v1 = *(const float4*)(D + (size_t)r * C_CLS + 4);
        d2v[r][0] = v0.x; d2v[r][1] = v0.y; d2v[r][2] = v0.z; d2v[r][3] = v0.w;
        d2v[r][4] = v1.x; d2v[r][5] = v1.y; d2v[r][6] = v1.z; d2v[r][7] = v1.w;
    }

    float sacc[8];
#pragma unroll
    for (int j = 0; j < 8; j++) sacc[j] = 0.0f;
    float sumA2 = 0.0f;
    float cnt   = 0.0f;

#pragma unroll
    for (int r = 0; r < 8; r++){
        float ss = 0.0f;
        float mv = 3.4e38f;
        int   mi = 1 << 30;
#pragma unroll
        for (int j = 0; j < 8; j++){
            const int   p = lane * 8 + j;
            const float v = d2v[r][j];
            if (v < mv){ mv = v; mi = p; }
            if (p != c) ss = fmaf(v, v, ss);
        }
#pragma unroll
        for (int off = 16; off; off >>= 1){
            ss += __shfl_xor_sync(0xffffffffu, ss, off);
            const float ov = __shfl_xor_sync(0xffffffffu, mv, off);
            const int   oi = __shfl_xor_sync(0xffffffffu, mi, off);
            if (ov < mv || (ov == mv && oi < mi)){ mv = ov; mi = oi; }
        }
        const float inv = 1.0f / fmaxf(sqrtf(ss), EPSF);
#pragma unroll
        for (int j = 0; j < 8; j++){
            const int p = lane * 8 + j;
            if (p != c) sacc[j] = fmaf(d2v[r][j], inv, sacc[j]);
        }
        if (lane == 0){
            sumA2 += ss * inv * inv;
            if (mi == c) cnt += 1.0f;
        }
    }

#pragma unroll
    for (int j = 0; j < 8; j++) s_part[w][lane * 8 + j] = sacc[j];
    if (lane == 0){
        atomicAdd(&s_scal[0], sumA2);
        atomicAdd(&s_scal[1], cnt);
    }
    __syncthreads();

    float col = 0.0f;
#pragma unroll
    for (int w2 = 0; w2 < 8; w2++) col += s_part[w2][tid];
    float sq = col * col;
#pragma unroll
    for (int off = 16; off; off >>= 1) sq += __shfl_xor_sync(0xffffffffu, sq, off);
    if (lane == 0) s_red[w] = sq;
    __syncthreads();
    if (tid == 0){
        float S2 = 0.0f;
#pragma unroll
        for (int i = 0; i < 8; i++) S2 += s_red[i];
        atomicAdd(&g_cos_sum, 0.5f * (S2 - s_scal[0]));
        atomicAdd(&g_acc_cnt, s_scal[1]);
    }
}

// ---------------- K5: finalize -------------------------------------------
__global__ void k_final(float* __restrict__ out){
    if (threadIdx.x == 0){
        out[0] = g_cos_sum / (float)NPAIRS;
        out[1] = g_acc_cnt / (float)CQ;
    }
}

// ---------------- launch ---------------------------------------------------
extern "C" void kernel_launch(void* const* d_in, const int* in_sizes, int n_in,
                              void* d_out, int out_size){
    const float* xs = (const float*)d_in[0];
    const float* xq = (const float*)d_in[1];
    const float* W  = (const float*)d_in[2];
    float* out = (float*)d_out;
    (void)in_sizes; (void)n_in; (void)out_size;

    const int smem_gemm = 2 * 16384 * (int)sizeof(float);   // 128 KB
    cudaFuncSetAttribute(k_gemm, cudaFuncAttributeMaxDynamicSharedMemorySize, smem_gemm);

    k_wsplit<<<NSTG, 256>>>(W);
    k_gemm<<<M_TOT / 128, 256, smem_gemm>>>(xs, xq);
    k_proto<<<C_CLS, 128>>>();
    k_d2<<<dim3(128, 2), 256>>>();
    k_loo<<<C_CLS, 256>>>();
    k_final<<<1, 1>>>(out);
}

// round 6
// speedup vs baseline: 1.2504x; 1.1183x over previous
#include <cuda_runtime.h>
#include <cstdint>

// Problem constants (fixed by reference setup_inputs)
#define C_CLS 256
#define S_SUP 5
#define Q_QRY 64
#define DIN   1024
#define ZD    128
#define CS    (C_CLS*S_SUP)              // 1280
#define CQ    (C_CLS*Q_QRY)              // 16384
#define M_TOT (CS+CQ)                    // 17664
#define NPAIRS (C_CLS*(Q_QRY*(Q_QRY-1)/2)) // 516096
#define EPSF  1e-8f
#define NSTG  64                          // k_gemm: K stages of 16
#define NST2  8                           // k_d2:   K stages of 16

// ---------------- device scratch (no allocations allowed) ----------------
__device__ __align__(16) float g_z[(size_t)M_TOT * ZD];        // ~9 MB
__device__ __align__(16) float g_d2[(size_t)CQ * C_CLS];       // 16 MB
__device__ __align__(16) float g_proto2[C_CLS];                // ||proto_c||^2
__device__ __align__(16) float g_row2[M_TOT];                  // ||z_row||^2
// W tf32 hi/lo images: flat [k8_idx(128)][n(128)][8 pos-permuted]
__device__ __align__(16) float g_Wh[128 * 1024];               // 512 KB
__device__ __align__(16) float g_Wl[128 * 1024];               // 512 KB
// protoT tf32 hi/lo images: [cb(2)][k8(16)][nn(128)][8]
__device__ __align__(16) float g_Ph[2 * 16 * 1024];            // 128 KB
__device__ __align__(16) float g_Pl[2 * 16 * 1024];            // 128 KB
__device__ float g_cos_sum;
__device__ float g_acc_cnt;

// ---------------- helpers ----------------
__device__ __forceinline__ uint32_t smem_u32(const void* p){
    uint32_t a; asm("{ .reg .u64 t; cvta.to.shared.u64 t, %1; cvt.u32.u64 %0, t; }"
                    : "=r"(a) : "l"(p));
    return a;
}
__device__ __forceinline__ float tf32_rna(float a){
    uint32_t r; asm("cvt.rna.tf32.f32 %0, %1;" : "=r"(r) : "f"(a));
    return __uint_as_float(r);
}
__device__ __forceinline__ void cp16(uint32_t saddr, const void* g){
    asm volatile("cp.async.cg.shared.global [%0], [%1], 16;" :: "r"(saddr), "l"(g));
}
#define CP_COMMIT() asm volatile("cp.async.commit_group;" ::: "memory")
#define CP_WAIT0()  asm volatile("cp.async.wait_group 0;"  ::: "memory")

// D += A(16x8,row) * B(8x8,col)   tf32 inputs, fp32 accum (validated R5)
__device__ __forceinline__ void mma8(float4 &d, float2 a01, float2 a23, float2 b){
    asm volatile("mma.sync.aligned.m16n8k8.row.col.f32.tf32.tf32.f32 "
        "{%0,%1,%2,%3}, {%4,%5,%6,%7}, {%8,%9}, {%0,%1,%2,%3};"
        : "+f"(d.x), "+f"(d.y), "+f"(d.z), "+f"(d.w)
        : "r"(__float_as_uint(a01.x)), "r"(__float_as_uint(a23.x)),
          "r"(__float_as_uint(a01.y)), "r"(__float_as_uint(a23.y)),
          "r"(__float_as_uint(b.x)),   "r"(__float_as_uint(b.y)));
}

// =====================================================================
// KW: split W[k=1024][n=128] into tf32 hi/lo images, pos-order
// [k0,k4,k1,k5,k2,k6,k3,k7] per k8-chunk row (validated R5 layout).
// =====================================================================
__global__ __launch_bounds__(256) void k_wsplit(const float* __restrict__ W){
    const int s   = blockIdx.x;          // 0..31 (covers 4 k8-chunks each)
    const int t   = threadIdx.x;
    const int n   = t >> 1;
    const int h   = t & 1;
#pragma unroll
    for (int kc = 0; kc < 4; kc++){
        const int kb = s * 32 + kc * 8 + 2 * h;
        const float v0 = W[(size_t)(kb + 0) * ZD + n];
        const float v1 = W[(size_t)(kb + 1) * ZD + n];
        const float v4 = W[(size_t)(kb + 4) * ZD + n];
        const float v5 = W[(size_t)(kb + 5) * ZD + n];
        const float h0 = tf32_rna(v0), h1 = tf32_rna(v1);
        const float h4 = tf32_rna(v4), h5 = tf32_rna(v5);
        const int off = (s * 4 + kc) * 1024 + n * 8 + h * 4;
        *(float4*)&g_Wh[off] = make_float4(h0, h4, h1, h5);
        *(float4*)&g_Wl[off] = make_float4(v0 - h0, v4 - h4, v1 - h1, v5 - h5);
    }
}

// =====================================================================
// K1: z = [xs; xq] @ W, mma.sync tf32 3-pass split.
// 512 threads = 16 warps (4m x 4n), warp tile 32x32, BK=16, 64 stages,
// double-buffered 2x32KB. B arrives via cp.async from the precomputed
// images (layout-identical); A is reg-prefetched, split hi/lo, STS'd.
// One __syncthreads per stage. Epilogue: z + fused ||row||^2.
// SMEM buf layout (8192 floats): [Ah 2048][Al 2048][Bh 2048][Bl 2048].
// =====================================================================
__global__ __launch_bounds__(512) void k_gemm(const float* __restrict__ xs,
                                              const float* __restrict__ xq){
    extern __shared__ float sb[];        // 2 x 8192 floats = 64 KB
    __shared__ float s_r2[128];

    const int tid  = threadIdx.x;
    const int lane = tid & 31;
    const int wid  = tid >> 5;
    const int g    = lane >> 2;
    const int tg   = lane & 3;
    const int m0   = (wid & 3) * 32;
    const int n0   = (wid >> 2) * 32;
    const int bm   = blockIdx.x;
    const float* X = (bm < 10) ? (xs + (size_t)bm * (128 * DIN))
                               : (xq + (size_t)(bm - 10) * (128 * DIN));
    // staging ids: 512 threads = 128 rows x 2 kc x 2 halves
    const int sm_m = tid >> 2;
    const int skc  = (tid >> 1) & 1;
    const int sh   = tid & 1;
    const int sts_off = skc * 1024 + sm_m * 8 + sh * 4;

    float4 acc[2][4];
#pragma unroll
    for (int i = 0; i < 2; i++)
#pragma unroll
        for (int j = 0; j < 4; j++) acc[i][j] = make_float4(0.f, 0.f, 0.f, 0.f);

    float4 rA;
    // prologue: stage 0
    {
        float* buf = sb;
        cp16(smem_u32(&buf[4096]) + tid * 16, g_Wh + tid * 4);
        cp16(smem_u32(&buf[6144]) + tid * 16, g_Wl + tid * 4);
        CP_COMMIT();
        const float* xp = X + (size_t)sm_m * DIN + skc * 8 + sh * 2;
        const float2 fa = *(const float2*)xp;
        const float2 fb = *(const float2*)(xp + 4);
        rA = make_float4(fa.x, fb.x, fa.y, fb.y);
        const float4 hi = make_float4(tf32_rna(rA.x), tf32_rna(rA.y),
                                      tf32_rna(rA.z), tf32_rna(rA.w));
        *(float4*)&buf[sts_off]        = hi;
        *(float4*)&buf[2048 + sts_off] = make_float4(rA.x - hi.x, rA.y - hi.y,
                                                     rA.z - hi.z, rA.w - hi.w);
        CP_WAIT0();
    }
    __syncthreads();

    for (int s = 0; s < NSTG; s++){
        const int b = s & 1;
        float* nbuf = sb + (b ^ 1) * 8192;
        if (s + 1 < NSTG){
            cp16(smem_u32(&nbuf[4096]) + tid * 16, g_Wh + (s + 1) * 2048 + tid * 4);
            cp16(smem_u32(&nbuf[6144]) + tid * 16, g_Wl + (s + 1) * 2048 + tid * 4);
            CP_COMMIT();
            const float* xp = X + (size_t)sm_m * DIN + (s + 1) * 16 + skc * 8 + sh * 2;
            const float2 fa = *(const float2*)xp;
            const float2 fb = *(const float2*)(xp + 4);
            rA = make_float4(fa.x, fb.x, fa.y, fb.y);
        }
        const float* buf = sb + b * 8192;
#pragma unroll
        for (int kc = 0; kc < 2; kc++){
            const float* Ah = buf + kc * 1024;
            const float* Al = Ah + 2048;
            const float* Bh = buf + 4096 + kc * 1024;
            const float* Bl = Bh + 2048;
            float2 bh[4], bl[4];
#pragma unroll
            for (int j = 0; j < 4; j++){
                const int nr = (n0 + j * 8 + g) * 8 + 2 * tg;
                bh[j] = *(const float2*)&Bh[nr];
                bl[j] = *(const float2*)&Bl[nr];
            }
#pragma unroll
            for (int mt = 0; mt < 2; mt++){
                const int r0 = (m0 + mt * 16 + g) * 8 + 2 * tg;
                const float2 ah01 = *(const float2*)&Ah[r0];
                const float2 ah23 = *(const float2*)&Ah[r0 + 64];
                const float2 al01 = *(const float2*)&Al[r0];
                const float2 al23 = *(const float2*)&Al[r0 + 64];
#pragma unroll
                for (int j = 0; j < 4; j++){
                    mma8(acc[mt][j], ah01, ah23, bh[j]);
                    mma8(acc[mt][j], al01, al23, bh[j]);
                    mma8(acc[mt][j], ah01, ah23, bl[j]);
                }
            }
        }
        if (s + 1 < NSTG){
            const float4 hi = make_float4(tf32_rna(rA.x), tf32_rna(rA.y),
                                          tf32_rna(rA.z), tf32_rna(rA.w));
            *(float4*)&nbuf[sts_off]        = hi;
            *(float4*)&nbuf[2048 + sts_off] = make_float4(rA.x - hi.x, rA.y - hi.y,
                                                          rA.z - hi.z, rA.w - hi.w);
            CP_WAIT0();
            __syncthreads();
        }
    }

    // ---- epilogue: z store + fused row norms ----
    if (tid < 128) s_r2[tid] = 0.0f;
    __syncthreads();
    const size_t rb = (size_t)bm * 128;
#pragma unroll
    for (int mt = 0; mt < 2; mt++){
        const int r0 = m0 + mt * 16 + g;
        float s0 = 0.0f, s1 = 0.0f;
#pragma unroll
        for (int j = 0; j < 4; j++){
            const float4 a = acc[mt][j];
            const int col = n0 + j * 8 + 2 * tg;
            *(float2*)(g_z + (rb + r0) * ZD + col)     = make_float2(a.x, a.y);
            *(float2*)(g_z + (rb + r0 + 8) * ZD + col) = make_float2(a.z, a.w);
            s0 = fmaf(a.x, a.x, s0); s0 = fmaf(a.y, a.y, s0);
            s1 = fmaf(a.z, a.z, s1); s1 = fmaf(a.w, a.w, s1);
        }
        s0 += __shfl_xor_sync(0xffffffffu, s0, 1);
        s0 += __shfl_xor_sync(0xffffffffu, s0, 2);
        s1 += __shfl_xor_sync(0xffffffffu, s1, 1);
        s1 += __shfl_xor_sync(0xffffffffu, s1, 2);
        if (tg == 0){
            atomicAdd(&s_r2[r0],     s0);
            atomicAdd(&s_r2[r0 + 8], s1);
        }
    }
    __syncthreads();
    if (tid < 128) g_row2[rb + tid] = s_r2[tid];
}

// ---------------- K2: prototypes + ||proto||^2 + hi/lo images -----------
__global__ __launch_bounds__(128) void k_proto(){
    const int c = blockIdx.x;
    const int d = threadIdx.x;  // 0..127 (= k index)
    if (c == 0 && d == 0){ g_cos_sum = 0.0f; g_acc_cnt = 0.0f; }
    const float* z = g_z + (size_t)c * S_SUP * ZD + d;
    float p = 0.0f;
#pragma unroll
    for (int s = 0; s < S_SUP; s++) p += z[s * ZD];
    p *= (1.0f / S_SUP);
    // write tf32 hi/lo image: [cb][k8][nn][pos]
    const int cb  = c >> 7, nn = c & 127;
    const int k8  = d >> 3;
    const int pos = ((d & 3) << 1) | ((d >> 2) & 1);
    const float hi = tf32_rna(p);
    const int off = (cb * 16 + k8) * 1024 + nn * 8 + pos;
    g_Ph[off] = hi;
    g_Pl[off] = p - hi;
    float sq = p * p;
#pragma unroll
    for (int off2 = 16; off2; off2 >>= 1) sq += __shfl_xor_sync(0xffffffffu, sq, off2);
    __shared__ float w[4];
    if ((d & 31) == 0) w[d >> 5] = sq;
    __syncthreads();
    if (d == 0) g_proto2[c] = w[0] + w[1] + w[2] + w[3];
}

// =====================================================================
// K3: d2 = ||zq||^2 + ||proto||^2 - 2 zq@protoT, mma.sync tf32 3-pass.
// Same engine as k_gemm: grid (128 qtiles, 2 cb), 512 thr, 8 stages.
// =====================================================================
__global__ __launch_bounds__(512) void k_d2(){
    extern __shared__ float sb[];        // 2 x 8192 floats = 64 KB
    const int tid  = threadIdx.x;
    const int lane = tid & 31;
    const int wid  = tid >> 5;
    const int g    = lane >> 2;
    const int tg   = lane & 3;
    const int m0   = (wid & 3) * 32;
    const int n0   = (wid >> 2) * 32;
    const int qb   = blockIdx.x;         // 0..127
    const int cb   = blockIdx.y;         // 0..1
    const float* X = g_z + (size_t)(CS + qb * 128) * ZD;
    const float* Ph = g_Ph + cb * 16384;
    const float* Pl = g_Pl + cb * 16384;
    const int sm_m = tid >> 2;
    const int skc  = (tid >> 1) & 1;
    const int sh   = tid & 1;
    const int sts_off = skc * 1024 + sm_m * 8 + sh * 4;

    float4 acc[2][4];
#pragma unroll
    for (int i = 0; i < 2; i++)
#pragma unroll
        for (int j = 0; j < 4; j++) acc[i][j] = make_float4(0.f, 0.f, 0.f, 0.f);

    float4 rA;
    {
        float* buf = sb;
        cp16(smem_u32(&buf[4096]) + tid * 16, Ph + tid * 4);
        cp16(smem_u32(&buf[6144]) + tid * 16, Pl + tid * 4);
        CP_COMMIT();
        const float* xp = X + (size_t)sm_m * ZD + skc * 8 + sh * 2;
        const float2 fa = *(const float2*)xp;
        const float2 fb = *(const float2*)(xp + 4);
        rA = make_float4(fa.x, fb.x, fa.y, fb.y);
        const float4 hi = make_float4(tf32_rna(rA.x), tf32_rna(rA.y),
                                      tf32_rna(rA.z), tf32_rna(rA.w));
        *(float4*)&buf[sts_off]        = hi;
        *(float4*)&buf[2048 + sts_off] = make_float4(rA.x - hi.x, rA.y - hi.y,
                                                     rA.z - hi.z, rA.w - hi.w);
        CP_WAIT0();
    }
    __syncthreads();

    for (int s = 0; s < NST2; s++){
        const int b = s & 1;
        float* nbuf = sb + (b ^ 1) * 8192;
        if (s + 1 < NST2){
            cp16(smem_u32(&nbuf[4096]) + tid * 16, Ph + (s + 1) * 2048 + tid * 4);
            cp16(smem_u32(&nbuf[6144]) + tid * 16, Pl + (s + 1) * 2048 + tid * 4);
            CP_COMMIT();
            const float* xp = X + (size_t)sm_m * ZD + (s + 1) * 16 + skc * 8 + sh * 2;
            const float2 fa = *(const float2*)xp;
            const float2 fb = *(const float2*)(xp + 4);
            rA = make_float4(fa.x, fb.x, fa.y, fb.y);
        }
        const float* buf = sb + b * 8192;
#pragma unroll
        for (int kc = 0; kc < 2; kc++){
            const float* Ah = buf + kc * 1024;
            const float* Al = Ah + 2048;
            const float* Bh = buf + 4096 + kc * 1024;
            const float* Bl = Bh + 2048;
            float2 bh[4], bl[4];
#pragma unroll
            for (int j = 0; j < 4; j++){
                const int nr = (n0 + j * 8 + g) * 8 + 2 * tg;
                bh[j] = *(const float2*)&Bh[nr];
                bl[j] = *(const float2*)&Bl[nr];
            }
#pragma unroll
            for (int mt = 0; mt < 2; mt++){
                const int r0 = (m0 + mt * 16 + g) * 8 + 2 * tg;
                const float2 ah01 = *(const float2*)&Ah[r0];
                const float2 ah23 = *(const float2*)&Ah[r0 + 64];
                const float2 al01 = *(const float2*)&Al[r0];
                const float2 al23 = *(const float2*)&Al[r0 + 64];
#pragma unroll
                for (int j = 0; j < 4; j++){
                    mma8(acc[mt][j], ah01, ah23, bh[j]);
                    mma8(acc[mt][j], al01, al23, bh[j]);
                    mma8(acc[mt][j], ah01, ah23, bl[j]);
                }
            }
        }
        if (s + 1 < NST2){
            const float4 hi = make_float4(tf32_rna(rA.x), tf32_rna(rA.y),
                                          tf32_rna(rA.z), tf32_rna(rA.w));
            *(float4*)&nbuf[sts_off]        = hi;
            *(float4*)&nbuf[2048 + sts_off] = make_float4(rA.x - hi.x, rA.y - hi.y,
                                                          rA.z - hi.z, rA.w - hi.w);
            CP_WAIT0();
            __syncthreads();
        }
    }

    // epilogue: d2 = qn + pn - 2*dot
#pragma unroll
    for (int mt = 0; mt < 2; mt++){
        const int r    = m0 + mt * 16 + g;
        const int grow = qb * 128 + r;
        const float qn0 = g_row2[CS + grow];
        const float qn1 = g_row2[CS + grow + 8];
#pragma unroll
        for (int j = 0; j < 4; j++){
            const int gcol = cb * 128 + n0 + j * 8 + 2 * tg;
            const float pn0 = g_proto2[gcol];
            const float pn1 = g_proto2[gcol + 1];
            const float4 a = acc[mt][j];
            *(float2*)(g_d2 + (size_t)grow * C_CLS + gcol) =
                make_float2(qn0 + pn0 - 2.0f * a.x, qn0 + pn1 - 2.0f * a.y);
            *(float2*)(g_d2 + (size_t)(grow + 8) * C_CLS + gcol) =
                make_float2(qn1 + pn0 - 2.0f * a.z, qn1 + pn1 - 2.0f * a.w);
        }
    }
}

// =====================================================================
// K4: per-class loo-norm + cos identity + argmin. 512 thr, 4 rows/warp.
// cos: sum_{q<k} a_q.a_k = ( ||sum_q a_q||^2 - sum_q ||a_q||^2 ) / 2
// =====================================================================
__global__ __launch_bounds__(512) void k_loo(){
    __shared__ float s_part[16][256];
    __shared__ float s_red[8];
    __shared__ float s_scal[2];

    const int tid  = threadIdx.x;
    const int c    = blockIdx.x;
    const int w    = tid >> 5;           // 0..15
    const int lane = tid & 31;
    if (tid < 2) s_scal[tid] = 0.0f;
    __syncthreads();

    const float* D = g_d2 + ((size_t)c * Q_QRY + w * 4) * C_CLS + lane * 8;
    float d2v[4][8];
#pragma unroll
    for (int r = 0; r < 4; r++){
        const float4 v0 = *(const float4*)(D + (size_t)r * C_CLS);
        const float4 v1 = *(const float4*)(D + (size_t)r * C_CLS + 4);
        d2v[r][0] = v0.x; d2v[r][1] = v0.y; d2v[r][2] = v0.z; d2v[r][3] = v0.w;
        d2v[r][4] = v1.x; d2v[r][5] = v1.y; d2v[r][6] = v1.z; d2v[r][7] = v1.w;
    }

    float sacc[8];
#pragma unroll
    for (int j = 0; j < 8; j++) sacc[j] = 0.0f;
    float sumA2 = 0.0f;
    float cnt   = 0.0f;

#pragma unroll
    for (int r = 0; r < 4; r++){
        float ss = 0.0f;
        float mv = 3.4e38f;
        int   mi = 1 << 30;
#pragma unroll
        for (int j = 0; j < 8; j++){
            const int   p = lane * 8 + j;
            const float v = d2v[r][j];
            if (v < mv){ mv = v; mi = p; }        // ascending -> first min
            if (p != c) ss = fmaf(v, v, ss);
        }
#pragma unroll
        for (int off = 16; off; off >>= 1){
            ss += __shfl_xor_sync(0xffffffffu, ss, off);
            const float ov = __shfl_xor_sync(0xffffffffu, mv, off);
            const int   oi = __shfl_xor_sync(0xffffffffu, mi, off);
            if (ov < mv || (ov == mv && oi < mi)){ mv = ov; mi = oi; }
        }
        const float inv = 1.0f / fmaxf(sqrtf(ss), EPSF);
#pragma unroll
        for (int j = 0; j < 8; j++){
            const int p = lane * 8 + j;
            if (p != c) sacc[j] = fmaf(d2v[r][j], inv, sacc[j]);
        }
        if (lane == 0){
            sumA2 += ss * inv * inv;
            if (mi == c) cnt += 1.0f;
        }
    }

#pragma unroll
    for (int j = 0; j < 8; j++) s_part[w][lane * 8 + j] = sacc[j];
    if (lane == 0){
        atomicAdd(&s_scal[0], sumA2);
        atomicAdd(&s_scal[1], cnt);
    }
    __syncthreads();

    if (tid < 256){
        float col = 0.0f;
#pragma unroll
        for (int w2 = 0; w2 < 16; w2++) col += s_part[w2][tid];
        float sq = col * col;
#pragma unroll
        for (int off = 16; off; off >>= 1) sq += __shfl_xor_sync(0xffffffffu, sq, off);
        if (lane == 0) s_red[tid >> 5] = sq;
    }
    __syncthreads();
    if (tid == 0){
        float S2 = 0.0f;
#pragma unroll
        for (int i = 0; i < 8; i++) S2 += s_red[i];
        atomicAdd(&g_cos_sum, 0.5f * (S2 - s_scal[0]));
        atomicAdd(&g_acc_cnt, s_scal[1]);
    }
}

// ---------------- K5: finalize -------------------------------------------
__global__ void k_final(float* __restrict__ out){
    if (threadIdx.x == 0){
        out[0] = g_cos_sum / (float)NPAIRS;
        out[1] = g_acc_cnt / (float)CQ;
    }
}

// ---------------- launch ---------------------------------------------------
extern "C" void kernel_launch(void* const* d_in, const int* in_sizes, int n_in,
                              void* d_out, int out_size){
    const float* xs = (const float*)d_in[0];
    const float* xq = (const float*)d_in[1];
    const float* W  = (const float*)d_in[2];
    float* out = (float*)d_out;
    (void)in_sizes; (void)n_in; (void)out_size;

    const int smem64 = 2 * 8192 * (int)sizeof(float);   // 64 KB
    cudaFuncSetAttribute(k_gemm, cudaFuncAttributeMaxDynamicSharedMemorySize, smem64);
    cudaFuncSetAttribute(k_d2,   cudaFuncAttributeMaxDynamicSharedMemorySize, smem64);

    k_wsplit<<<32, 256>>>(W);
    k_gemm<<<M_TOT / 128, 512, smem64>>>(xs, xq);
    k_proto<<<C_CLS, 128>>>();
    k_d2<<<dim3(128, 2), 512, smem64>>>();
    k_loo<<<C_CLS, 512>>>();
    k_final<<<1, 1>>>(out);
}